// round 16
// baseline (speedup 1.0000x reference)
#include <cuda_runtime.h>
#include <math.h>
#include <stdint.h>

#define BB 64
#define TT 512
#define II 512
#define HH 1024
#define OO 512
#define MM 64
#define PP 1024
#define G3 3072
#define NB 148
#define NT 512

#define STAGE_BYTES 49152u        // X 16KB + W 32KB per stage

__device__ __align__(16) float g_h[2][BB * HH];
__device__ __align__(16) float g_gi[2][BB * G3];    // gi K-splits (K=256)
__device__ __align__(16) float g_gh[4][BB * G3];    // gh K-splits (K=256)
__device__ __align__(16) float g_cp[4][BB * OO];    // out K-splits (K=256)
__device__ __align__(16) float g_memT[MM * PP];
__device__ __align__(16) float g_WriT[MM * II];     // transposed Wri
// pre-converted bf16 hi/lo weight image (see R15): gi[0,192) gh[192,576) out[576,640)
__device__ __align__(16) uint32_t g_Wpre[640 * 8192];      // 20 MB
__device__ __align__(16) uint32_t g_hpre[2][16 * 4096];
__device__ __align__(16) uint32_t g_xpre[8 * 4096];
__device__ volatile unsigned g_gen;
__device__ unsigned g_cnt;

static __device__ __forceinline__ uint32_t smem_u32(const void* p)
{
    uint32_t a;
    asm("{ .reg .u64 t; cvta.to.shared.u64 t, %1; cvt.u32.u64 %0, t; }"
        : "=r"(a) : "l"(p));
    return a;
}

static __device__ __forceinline__ void cp16(uint32_t dst, const void* src)
{
    asm volatile("cp.async.cg.shared.global [%0], [%1], 16;"
                 :: "r"(dst), "l"(src));
}

__device__ __forceinline__ void gsync()
{
    __syncthreads();
    __threadfence();
    if (threadIdx.x == 0) {
        unsigned my = g_gen;
        if (atomicAdd(&g_cnt, 1u) == NB - 1u) {
            atomicExch(&g_cnt, 0u);
            __threadfence();
            g_gen = my + 1u;
        } else {
            while (g_gen == my) { __nanosleep(64); }
        }
    }
    __syncthreads();
    __threadfence();
}

static __device__ __forceinline__ uint32_t pack2(float lo, float hi)
{
    uint32_t r;
    asm("cvt.rn.bf16x2.f32 %0, %1, %2;" : "=r"(r) : "f"(hi), "f"(lo));
    return r;
}

static __device__ __forceinline__ void ldsm4(uint32_t& r0, uint32_t& r1,
                                             uint32_t& r2, uint32_t& r3,
                                             uint32_t a)
{
    asm volatile("ldmatrix.sync.aligned.m8n8.x4.shared.b16 {%0,%1,%2,%3}, [%4];"
                 : "=r"(r0), "=r"(r1), "=r"(r2), "=r"(r3) : "r"(a));
}

static __device__ __forceinline__ void mma4(float* d, const uint32_t* a,
                                            uint32_t b0, uint32_t b1)
{
    asm volatile(
        "mma.sync.aligned.m16n8k16.row.col.f32.bf16.bf16.f32 "
        "{%0,%1,%2,%3}, {%4,%5,%6,%7}, {%8,%9}, {%0,%1,%2,%3};"
        : "+f"(d[0]), "+f"(d[1]), "+f"(d[2]), "+f"(d[3])
        : "r"(a[0]), "r"(a[1]), "r"(a[2]), "r"(a[3]), "r"(b0), "r"(b1));
}

// ---------------------------------------------------------------------------
// HMMA job (identical to R15): D[64 x 128] partial from pre-packed bf16 images.
// ---------------------------------------------------------------------------
static __device__ void hjob(const uint32_t* __restrict__ preX,
                            const uint32_t* __restrict__ preW,
                            int nch, float* __restrict__ outp, int ldo,
                            int n0, uint32_t sb)
{
    const int tid = threadIdx.x;
    const int l   = tid & 31;
    const int wrp = tid >> 5;
    const int rg  = wrp & 3;
    const int cg  = wrp >> 2;

    float d[4][4];
    #pragma unroll
    for (int i = 0; i < 4; i++)
        d[i][0] = d[i][1] = d[i][2] = d[i][3] = 0.f;

    const int am    = l >> 3;
    const int alr   = l & 7;
    const int arow  = rg * 16 + ((am & 1) << 3) + alr;
    const uint32_t arow_off = (uint32_t)arow * 128u;
    const int ahalf = am >> 1;
    const int aswz  = arow & 7;
    const int brow0 = cg * 32 + ((am >> 1) << 3) + alr;
    const int bhalf = am & 1;

    auto issue = [&](int c) {
        if (c >= nch) return;
        uint32_t st = sb + (uint32_t)(c % 3) * STAGE_BYTES;
        const uint32_t* px = preX + (size_t)c * 4096;
        const uint32_t* pw = preW + (size_t)c * 8192;
        cp16(st + (uint32_t)tid * 16u, px + tid * 4);
        cp16(st + 8192u + (uint32_t)tid * 16u, px + 2048 + tid * 4);
        #pragma unroll
        for (int q = 0; q < 4; q++)
            cp16(st + 16384u + (uint32_t)(tid + q * 512) * 16u,
                 pw + (tid + q * 512) * 4);
        asm volatile("cp.async.commit_group;" ::: "memory");
    };

    issue(0);
    issue(1);

    for (int c = 0; c < nch; c++) {
        if (c + 1 < nch)
            asm volatile("cp.async.wait_group 1;" ::: "memory");
        else
            asm volatile("cp.async.wait_group 0;" ::: "memory");
        __syncthreads();

        uint32_t st = sb + (uint32_t)(c % 3) * STAGE_BYTES;
        #pragma unroll
        for (int s = 0; s < 4; s++) {
            uint32_t ao = (uint32_t)((s * 2 + ahalf) ^ aswz) << 4;
            uint32_t Ah[4], Al[4];
            ldsm4(Ah[0], Ah[1], Ah[2], Ah[3], st + arow_off + ao);
            ldsm4(Al[0], Al[1], Al[2], Al[3], st + 8192u + arow_off + ao);
            uint32_t Bh[2][4], Bl[2][4];
            #pragma unroll
            for (int p = 0; p < 2; p++) {
                int brow = brow0 + p * 16;
                uint32_t bo = (uint32_t)brow * 128u
                            + ((uint32_t)((s * 2 + bhalf) ^ (brow & 7)) << 4);
                ldsm4(Bh[p][0], Bh[p][1], Bh[p][2], Bh[p][3], st + 16384u + bo);
                ldsm4(Bl[p][0], Bl[p][1], Bl[p][2], Bl[p][3], st + 32768u + bo);
            }
            #pragma unroll
            for (int nt = 0; nt < 4; nt++) {
                int p = nt >> 1, u = (nt & 1) << 1;
                mma4(d[nt], Ah, Bh[p][u], Bh[p][u + 1]);
                mma4(d[nt], Ah, Bl[p][u], Bl[p][u + 1]);
                mma4(d[nt], Al, Bh[p][u], Bh[p][u + 1]);
            }
        }

        issue(c + 2);
    }

    #pragma unroll
    for (int nt = 0; nt < 4; nt++) {
        int col  = n0 + cg * 32 + nt * 8 + (l & 3) * 2;
        int row0 = rg * 16 + (l >> 2);
        *(float2*)(outp + (size_t)row0 * ldo + col) = make_float2(d[nt][0], d[nt][1]);
        *(float2*)(outp + (size_t)(row0 + 8) * ldo + col) = make_float2(d[nt][2], d[nt][3]);
    }
}

// ---------------------------------------------------------------------------
// Phase A, 4 batch rows per block (rows b0..b0+3). All streamed operands
// loaded once, reused x4 via [idx][4] interleaved smem layouts.
// smem (floats): hs[1024][4] | ex[1024][4] | kq[64][4] | red[8][64][4]
//                | rv[64][4] | sMx[16][4] | sSm[16][4]   (~43.5 KB)
// ---------------------------------------------------------------------------
static __device__ void phaseA4(int b0, int t,
                               const float* __restrict__ hcur,
                               const float* __restrict__ x,
                               const float* __restrict__ mem,
                               const float* __restrict__ Wk,
                               const float* __restrict__ bk,
                               const float* __restrict__ bri,
                               float* sm)
{
    float* hs  = sm;           // [1024][4]
    float* ex  = sm + 4096;    // [1024][4]
    float* kq  = sm + 8192;    // [64][4]
    float* red = sm + 8448;    // [8][64][4]
    float* rv  = sm + 10496;   // [64][4]
    float* sMx = sm + 10752;   // [16][4]
    float* sSm = sm + 10816;   // [16][4]

    const int tid  = threadIdx.x;
    const int warp = tid >> 5;
    const int lane = tid & 31;

    // load h rows (interleaved [c][r])
    #pragma unroll
    for (int q = 0; q < 8; q++) {
        int idx = tid + q * 512;
        int r = idx >> 10, c = idx & 1023;
        hs[c * 4 + r] = hcur[(size_t)(b0 + r) * HH + c];
    }
    __syncthreads();

    // kq[m][r] = sum_k h[r][k] * Wk[m][k] + bk[m]; warp -> m = warp*4+mi
    {
        float a[4][4];
        #pragma unroll
        for (int mi = 0; mi < 4; mi++)
            a[mi][0] = a[mi][1] = a[mi][2] = a[mi][3] = 0.f;
        const float* w0 = Wk + (size_t)(warp * 4) * HH;
        #pragma unroll 4
        for (int j = 0; j < 32; j++) {
            int k = lane + j * 32;
            float4 hv = *(const float4*)&hs[k * 4];
            float w0v = w0[k], w1v = w0[HH + k], w2v = w0[2 * HH + k], w3v = w0[3 * HH + k];
            a[0][0] += w0v * hv.x; a[0][1] += w0v * hv.y; a[0][2] += w0v * hv.z; a[0][3] += w0v * hv.w;
            a[1][0] += w1v * hv.x; a[1][1] += w1v * hv.y; a[1][2] += w1v * hv.z; a[1][3] += w1v * hv.w;
            a[2][0] += w2v * hv.x; a[2][1] += w2v * hv.y; a[2][2] += w2v * hv.z; a[2][3] += w2v * hv.w;
            a[3][0] += w3v * hv.x; a[3][1] += w3v * hv.y; a[3][2] += w3v * hv.z; a[3][3] += w3v * hv.w;
        }
        #pragma unroll
        for (int mi = 0; mi < 4; mi++)
            #pragma unroll
            for (int r = 0; r < 4; r++)
                #pragma unroll
                for (int off = 16; off; off >>= 1)
                    a[mi][r] += __shfl_down_sync(0xffffffffu, a[mi][r], off);
        if (lane == 0) {
            #pragma unroll
            for (int mi = 0; mi < 4; mi++) {
                int m = warp * 4 + mi;
                float bv = bk[m];
                *(float4*)&kq[m * 4] = make_float4(a[mi][0] + bv, a[mi][1] + bv,
                                                   a[mi][2] + bv, a[mi][3] + bv);
            }
        }
    }
    __syncthreads();

    // scores: slots {tid, tid+512} for all 4 rows
    float sc[2][4];
    #pragma unroll
    for (int u = 0; u < 2; u++)
        sc[u][0] = sc[u][1] = sc[u][2] = sc[u][3] = 0.f;
    {
        const float* mt = g_memT + tid;
        #pragma unroll 8
        for (int m = 0; m < MM; m++) {
            float4 kv = *(const float4*)&kq[m * 4];
            float m0 = mt[(size_t)m * PP];
            float m1 = mt[(size_t)m * PP + 512];
            sc[0][0] += kv.x * m0; sc[0][1] += kv.y * m0; sc[0][2] += kv.z * m0; sc[0][3] += kv.w * m0;
            sc[1][0] += kv.x * m1; sc[1][1] += kv.y * m1; sc[1][2] += kv.z * m1; sc[1][3] += kv.w * m1;
        }
    }
    // per-row block max
    {
        float mx[4];
        #pragma unroll
        for (int r = 0; r < 4; r++) {
            mx[r] = fmaxf(sc[0][r], sc[1][r]);
            #pragma unroll
            for (int off = 16; off; off >>= 1)
                mx[r] = fmaxf(mx[r], __shfl_xor_sync(0xffffffffu, mx[r], off));
        }
        if (lane == 0)
            *(float4*)&sMx[warp * 4] = make_float4(mx[0], mx[1], mx[2], mx[3]);
    }
    __syncthreads();
    float bm[4];
    {
        float4 v = *(const float4*)&sMx[0];
        bm[0] = v.x; bm[1] = v.y; bm[2] = v.z; bm[3] = v.w;
        #pragma unroll
        for (int w = 1; w < 16; w++) {
            float4 u = *(const float4*)&sMx[w * 4];
            bm[0] = fmaxf(bm[0], u.x); bm[1] = fmaxf(bm[1], u.y);
            bm[2] = fmaxf(bm[2], u.z); bm[3] = fmaxf(bm[3], u.w);
        }
    }
    // exp + store + row sums
    float ls[4] = {0.f, 0.f, 0.f, 0.f};
    #pragma unroll
    for (int u = 0; u < 2; u++) {
        float e0 = expf(sc[u][0] - bm[0]);
        float e1 = expf(sc[u][1] - bm[1]);
        float e2 = expf(sc[u][2] - bm[2]);
        float e3 = expf(sc[u][3] - bm[3]);
        *(float4*)&ex[(tid + u * 512) * 4] = make_float4(e0, e1, e2, e3);
        ls[0] += e0; ls[1] += e1; ls[2] += e2; ls[3] += e3;
    }
    #pragma unroll
    for (int r = 0; r < 4; r++)
        #pragma unroll
        for (int off = 16; off; off >>= 1)
            ls[r] += __shfl_xor_sync(0xffffffffu, ls[r], off);
    if (lane == 0)
        *(float4*)&sSm[warp * 4] = make_float4(ls[0], ls[1], ls[2], ls[3]);
    __syncthreads();
    float bs[4] = {0.f, 0.f, 0.f, 0.f};
    #pragma unroll
    for (int w = 0; w < 16; w++) {
        float4 u = *(const float4*)&sSm[w * 4];
        bs[0] += u.x; bs[1] += u.y; bs[2] += u.z; bs[3] += u.w;
    }

    // read partials: q = tid>>6 (8 groups of 128 p), m = tid&63
    {
        int m = tid & 63, q = tid >> 6;
        const float* mp = mem + (size_t)(q * 128) * MM + m;
        float pr0 = 0.f, pr1 = 0.f, pr2 = 0.f, pr3 = 0.f;
        const float* ep = ex + (q * 128) * 4;
        #pragma unroll 8
        for (int p = 0; p < 128; p++) {
            float mv = mp[(size_t)p * MM];
            float4 ev = *(const float4*)&ep[p * 4];
            pr0 += ev.x * mv; pr1 += ev.y * mv; pr2 += ev.z * mv; pr3 += ev.w * mv;
        }
        *(float4*)&red[(q * 64 + m) * 4] = make_float4(pr0, pr1, pr2, pr3);
    }
    __syncthreads();
    if (tid < MM) {
        float s0 = 0.f, s1 = 0.f, s2 = 0.f, s3 = 0.f;
        #pragma unroll
        for (int q = 0; q < 8; q++) {
            float4 v = *(const float4*)&red[(q * 64 + tid) * 4];
            s0 += v.x; s1 += v.y; s2 += v.z; s3 += v.w;
        }
        *(float4*)&rv[tid * 4] = make_float4(s0 / bs[0], s1 / bs[1],
                                             s2 / bs[2], s3 / bs[3]);
    }
    __syncthreads();

    // xin: col i = tid for all 4 rows; write bf16 image directly
    {
        int i = tid;
        float bv = bri[i];
        float a0 = bv, a1 = bv, a2 = bv, a3 = bv;
        const float* wt = g_WriT + i;
        #pragma unroll 8
        for (int m = 0; m < MM; m++) {
            float wv = wt[(size_t)m * II];
            float4 rvv = *(const float4*)&rv[m * 4];
            a0 += rvv.x * wv; a1 += rvv.y * wv; a2 += rvv.z * wv; a3 += rvv.w * wv;
        }
        float vr[4];
        vr[0] = x[((size_t)(b0 + 0) * TT + t) * II + i] + fmaxf(a0, 0.f);
        vr[1] = x[((size_t)(b0 + 1) * TT + t) * II + i] + fmaxf(a1, 0.f);
        vr[2] = x[((size_t)(b0 + 2) * TT + t) * II + i] + fmaxf(a2, 0.f);
        vr[3] = x[((size_t)(b0 + 3) * TT + t) * II + i] + fmaxf(a3, 0.f);
        #pragma unroll
        for (int r = 0; r < 4; r++) {
            float v = vr[r];
            float vn = __shfl_down_sync(0xffffffffu, v, 1);
            if ((i & 1) == 0) {
                uint32_t hi = pack2(v, vn);
                float r0 = v  - __uint_as_float(hi << 16);
                float r1 = vn - __uint_as_float(hi & 0xFFFF0000u);
                uint32_t lo = pack2(r0, r1);
                int b = b0 + r;
                int kc = i >> 6, f2 = (i & 63) >> 1;
                int word = kc * 4096 + b * 32 + (f2 ^ ((b & 7) << 2));
                g_xpre[word]        = hi;
                g_xpre[word + 2048] = lo;
            }
        }
    }
    __syncthreads();
}

// ---------------------------------------------------------------------------
// Persistent megakernel.
//   S1: phaseA4 [0..15] || out(t-1) 16 jobs [16..31] || gh ALL 96 [32..127]
//   S2: gi 48 jobs [0..47]
//   S3: GRU [0..127] || out combine+store(t-1) [128..147]
// ---------------------------------------------------------------------------
__global__ void __launch_bounds__(NT, 1) ntm_persist(
    const float* __restrict__ x,    const float* __restrict__ mem,
    const float* __restrict__ Wk,   const float* __restrict__ bk,
    const float* __restrict__ Wri,  const float* __restrict__ bri,
    const float* __restrict__ Wih,  const float* __restrict__ Whh,
    const float* __restrict__ bih,  const float* __restrict__ bhh,
    const float* __restrict__ Wout, const float* __restrict__ bout,
    float* __restrict__ out)
{
    extern __shared__ __align__(16) char dsm[];     // 3 stages = 147,456 B
    const uint32_t sb = smem_u32(dsm);
    float* smf = (float*)dsm;

    const int bid = blockIdx.x;
    const int tid = threadIdx.x;
    const int gid = bid * NT + tid;

    // ---- one-time init ----
    for (int e = gid; e < BB * HH; e += NB * NT) g_h[0][e] = 0.f;
    for (int e = gid; e < 16 * 4096; e += NB * NT) g_hpre[0][e] = 0u;
    for (int e = gid; e < PP * MM; e += NB * NT) {
        int p = e >> 6, m = e & 63;
        g_memT[m * PP + p] = mem[e];
    }
    for (int e = gid; e < MM * II; e += NB * NT) {
        int m = e >> 9, i = e & 511;
        g_WriT[m * II + i] = Wri[(size_t)i * MM + m];
    }
    for (int w = gid; w < 640 * 4096; w += NB * NT) {
        int blk = w >> 12, within = w & 4095;
        int r = within >> 5, sw = within & 31;
        int f2 = sw ^ ((r & 7) << 2);
        const float* src; int ldw, row, k;
        if (blk < 192) {
            int ct = blk >> 3, kc = blk & 7;
            src = Wih; ldw = II; row = ct * 128 + r; k = kc * 64 + f2 * 2;
        } else if (blk < 576) {
            int b2 = blk - 192, ct = b2 >> 4, kc = b2 & 15;
            src = Whh; ldw = HH; row = ct * 128 + r; k = kc * 64 + f2 * 2;
        } else {
            int b3 = blk - 576, ct = b3 >> 4, kc = b3 & 15;
            src = Wout; ldw = HH; row = ct * 128 + r; k = kc * 64 + f2 * 2;
        }
        float v0 = src[(size_t)row * ldw + k];
        float v1 = src[(size_t)row * ldw + k + 1];
        uint32_t hi = pack2(v0, v1);
        float r0 = v0 - __uint_as_float(hi << 16);
        float r1 = v1 - __uint_as_float(hi & 0xFFFF0000u);
        uint32_t lo = pack2(r0, r1);
        g_Wpre[(size_t)blk * 8192 + within]        = hi;
        g_Wpre[(size_t)blk * 8192 + 4096 + within] = lo;
    }
    gsync();

    for (int t = 0; t <= TT; t++) {
        const float* hcur = g_h[t & 1];
        const uint32_t* hpre = g_hpre[t & 1];

        // ---- S1 ----
        if (bid < 16) {
            if (t < TT) phaseA4(bid * 4, t, hcur, x, mem, Wk, bk, bri, smf);
        } else if (bid < 32) {
            if (t >= 1) {
                int j = bid - 16, ct = j >> 2, ks = j & 3;
                hjob(hpre + ks * 4 * 4096,
                     g_Wpre + (size_t)(576 + ct * 16 + ks * 4) * 8192,
                     4, g_cp[ks], OO, ct * 128, sb);
            }
        } else if (bid < 128) {
            if (t < TT) {
                int j = bid - 32, ct = j >> 2, ks = j & 3;
                hjob(hpre + ks * 4 * 4096,
                     g_Wpre + (size_t)(192 + ct * 16 + ks * 4) * 8192,
                     4, g_gh[ks], G3, ct * 128, sb);
            }
        }
        gsync();

        // ---- S2: gi ----
        if (t < TT && bid < 48) {
            int ct = bid >> 1, ks = bid & 1;
            hjob(g_xpre + ks * 4 * 4096,
                 g_Wpre + (size_t)(ct * 8 + ks * 4) * 8192,
                 4, g_gi[ks], G3, ct * 128, sb);
        }
        gsync();

        // ---- S3: GRU [0..127] || out combine(t-1) [128..147] ----
        if (bid < 128) {
            if (t < TT) {
                float* hnew = g_h[(t + 1) & 1];
                uint32_t* hp = g_hpre[(t + 1) & 1];
                int e = gid;                          // 0..65535
                int b = e >> 10, c = e & 1023;
                size_t o = (size_t)b * G3 + c;
                float ir  = g_gi[0][o]        + g_gi[1][o]        + bih[c];
                float iz  = g_gi[0][o + 1024] + g_gi[1][o + 1024] + bih[1024 + c];
                float inn = g_gi[0][o + 2048] + g_gi[1][o + 2048] + bih[2048 + c];
                float hr = bhh[c], hz = bhh[1024 + c], hn = bhh[2048 + c];
                #pragma unroll
                for (int q = 0; q < 4; q++) {
                    hr += g_gh[q][o];
                    hz += g_gh[q][o + 1024];
                    hn += g_gh[q][o + 2048];
                }
                float rg = 1.f / (1.f + expf(-(ir + hr)));
                float zg = 1.f / (1.f + expf(-(iz + hz)));
                float ng = tanhf(inn + rg * hn);
                float hv = (1.f - zg) * ng + zg * hcur[e];
                hnew[e] = hv;
                float vn = __shfl_down_sync(0xffffffffu, hv, 1);
                if ((e & 1) == 0) {
                    uint32_t hi = pack2(hv, vn);
                    float r0 = hv - __uint_as_float(hi << 16);
                    float r1 = vn - __uint_as_float(hi & 0xFFFF0000u);
                    uint32_t lo = pack2(r0, r1);
                    int kc = c >> 6, f2 = (c & 63) >> 1;
                    int word = kc * 4096 + b * 32 + (f2 ^ ((b & 7) << 2));
                    hp[word]        = hi;
                    hp[word + 2048] = lo;
                }
            }
        } else if (t >= 1) {
            for (int e = (bid - 128) * NT + tid; e < BB * OO; e += 20 * NT) {
                int b = e >> 9, oc = e & (OO - 1);
                float s = bout[oc] + g_cp[0][e] + g_cp[1][e]
                        + g_cp[2][e] + g_cp[3][e];
                out[((size_t)b * TT + (t - 1)) * OO + oc] = 1.f / (1.f + expf(-s));
            }
        }
        if (t == TT) break;
        gsync();
    }
}

extern "C" void kernel_launch(void* const* d_in, const int* in_sizes, int n_in,
                              void* d_out, int out_size)
{
    const float* x    = (const float*)d_in[0];
    const float* mem  = (const float*)d_in[1];
    const float* Wk   = (const float*)d_in[2];
    const float* bk   = (const float*)d_in[3];
    const float* Wri  = (const float*)d_in[4];
    const float* bri  = (const float*)d_in[5];
    const float* Wih  = (const float*)d_in[6];
    const float* Whh  = (const float*)d_in[7];
    const float* bih  = (const float*)d_in[8];
    const float* bhh  = (const float*)d_in[9];
    const float* Wout = (const float*)d_in[10];
    const float* bout = (const float*)d_in[11];

    static int once = 0;
    const int smem_bytes = 3 * STAGE_BYTES;   // 147,456
    if (!once) {
        cudaFuncSetAttribute(ntm_persist,
                             cudaFuncAttributeMaxDynamicSharedMemorySize,
                             smem_bytes);
        once = 1;
    }

    ntm_persist<<<NB, NT, smem_bytes>>>(x, mem, Wk, bk, Wri, bri, Wih, Whh,
                                        bih, bhh, Wout, bout, (float*)d_out);
}

// round 17
// speedup vs baseline: 1.0585x; 1.0585x over previous
#include <cuda_runtime.h>
#include <math.h>
#include <stdint.h>

#define BB 64
#define TT 512
#define II 512
#define HH 1024
#define OO 512
#define MM 64
#define PP 1024
#define G3 3072
#define NB 148
#define NT 512

#define STAGE_BYTES 49152u        // X 16KB + W 32KB per stage

__device__ __align__(16) float g_h[2][BB * HH];
__device__ __align__(16) float g_gi[2][BB * G3];    // gi K-splits (K=256)
__device__ __align__(16) float g_gh[4][BB * G3];    // gh K-splits (K=256)
__device__ __align__(16) float g_cp[4][BB * OO];    // out K-splits (K=256)
__device__ __align__(16) float g_memT[MM * PP];
// pre-converted bf16 hi/lo weight image: gi[0,192) gh[192,576) out[576,640)
__device__ __align__(16) uint32_t g_Wpre[640 * 8192];      // 20 MB
__device__ __align__(16) uint32_t g_hpre[2][16 * 4096];
__device__ __align__(16) uint32_t g_xpre[8 * 4096];
__device__ __align__(256) unsigned g_cnt8[8 * 64];  // distributed arrive counters
__device__ volatile unsigned g_gen;

static __device__ __forceinline__ uint32_t smem_u32(const void* p)
{
    uint32_t a;
    asm("{ .reg .u64 t; cvta.to.shared.u64 t, %1; cvt.u32.u64 %0, t; }"
        : "=r"(a) : "l"(p));
    return a;
}

static __device__ __forceinline__ void cp16(uint32_t dst, const void* src)
{
    asm volatile("cp.async.cg.shared.global [%0], [%1], 16;"
                 :: "r"(dst), "l"(src));
}

// ---------------------------------------------------------------------------
// Distributed grid barrier: 8-way arrive counters, block 0 releases.
// ---------------------------------------------------------------------------
__device__ __forceinline__ void gsync()
{
    __syncthreads();
    __threadfence();
    if (threadIdx.x == 0) {
        unsigned my = g_gen;
        atomicAdd(&g_cnt8[(blockIdx.x & 7) * 64], 1u);
        if (blockIdx.x == 0) {
            for (;;) {
                unsigned s = 0;
                #pragma unroll
                for (int i = 0; i < 8; i++)
                    s += *(volatile unsigned*)&g_cnt8[i * 64];
                if (s == NB) break;
                __nanosleep(32);
            }
            #pragma unroll
            for (int i = 0; i < 8; i++)
                *(volatile unsigned*)&g_cnt8[i * 64] = 0u;
            __threadfence();
            g_gen = my + 1u;
        } else {
            while (g_gen == my) __nanosleep(32);
        }
    }
    __syncthreads();
    __threadfence();
}

static __device__ __forceinline__ uint32_t pack2(float lo, float hi)
{
    uint32_t r;
    asm("cvt.rn.bf16x2.f32 %0, %1, %2;" : "=r"(r) : "f"(hi), "f"(lo));
    return r;
}

static __device__ __forceinline__ void ldsm4(uint32_t& r0, uint32_t& r1,
                                             uint32_t& r2, uint32_t& r3,
                                             uint32_t a)
{
    asm volatile("ldmatrix.sync.aligned.m8n8.x4.shared.b16 {%0,%1,%2,%3}, [%4];"
                 : "=r"(r0), "=r"(r1), "=r"(r2), "=r"(r3) : "r"(a));
}

static __device__ __forceinline__ void mma4(float* d, const uint32_t* a,
                                            uint32_t b0, uint32_t b1)
{
    asm volatile(
        "mma.sync.aligned.m16n8k16.row.col.f32.bf16.bf16.f32 "
        "{%0,%1,%2,%3}, {%4,%5,%6,%7}, {%8,%9}, {%0,%1,%2,%3};"
        : "+f"(d[0]), "+f"(d[1]), "+f"(d[2]), "+f"(d[3])
        : "r"(a[0]), "r"(a[1]), "r"(a[2]), "r"(a[3]), "r"(b0), "r"(b1));
}

// ---------------------------------------------------------------------------
// HMMA job: D[64 x 128] partial from pre-packed bf16 images (3-stage cp.async).
// ---------------------------------------------------------------------------
static __device__ void hjob(const uint32_t* __restrict__ preX,
                            const uint32_t* __restrict__ preW,
                            int nch, float* __restrict__ outp, int ldo,
                            int n0, uint32_t sb)
{
    const int tid = threadIdx.x;
    const int l   = tid & 31;
    const int wrp = tid >> 5;
    const int rg  = wrp & 3;
    const int cg  = wrp >> 2;

    float d[4][4];
    #pragma unroll
    for (int i = 0; i < 4; i++)
        d[i][0] = d[i][1] = d[i][2] = d[i][3] = 0.f;

    const int am    = l >> 3;
    const int alr   = l & 7;
    const int arow  = rg * 16 + ((am & 1) << 3) + alr;
    const uint32_t arow_off = (uint32_t)arow * 128u;
    const int ahalf = am >> 1;
    const int aswz  = arow & 7;
    const int brow0 = cg * 32 + ((am >> 1) << 3) + alr;
    const int bhalf = am & 1;

    auto issue = [&](int c) {
        if (c >= nch) return;
        uint32_t st = sb + (uint32_t)(c % 3) * STAGE_BYTES;
        const uint32_t* px = preX + (size_t)c * 4096;
        const uint32_t* pw = preW + (size_t)c * 8192;
        cp16(st + (uint32_t)tid * 16u, px + tid * 4);
        cp16(st + 8192u + (uint32_t)tid * 16u, px + 2048 + tid * 4);
        #pragma unroll
        for (int q = 0; q < 4; q++)
            cp16(st + 16384u + (uint32_t)(tid + q * 512) * 16u,
                 pw + (tid + q * 512) * 4);
        asm volatile("cp.async.commit_group;" ::: "memory");
    };

    issue(0);
    issue(1);

    for (int c = 0; c < nch; c++) {
        if (c + 1 < nch)
            asm volatile("cp.async.wait_group 1;" ::: "memory");
        else
            asm volatile("cp.async.wait_group 0;" ::: "memory");
        __syncthreads();

        uint32_t st = sb + (uint32_t)(c % 3) * STAGE_BYTES;
        #pragma unroll
        for (int s = 0; s < 4; s++) {
            uint32_t ao = (uint32_t)((s * 2 + ahalf) ^ aswz) << 4;
            uint32_t Ah[4], Al[4];
            ldsm4(Ah[0], Ah[1], Ah[2], Ah[3], st + arow_off + ao);
            ldsm4(Al[0], Al[1], Al[2], Al[3], st + 8192u + arow_off + ao);
            uint32_t Bh[2][4], Bl[2][4];
            #pragma unroll
            for (int p = 0; p < 2; p++) {
                int brow = brow0 + p * 16;
                uint32_t bo = (uint32_t)brow * 128u
                            + ((uint32_t)((s * 2 + bhalf) ^ (brow & 7)) << 4);
                ldsm4(Bh[p][0], Bh[p][1], Bh[p][2], Bh[p][3], st + 16384u + bo);
                ldsm4(Bl[p][0], Bl[p][1], Bl[p][2], Bl[p][3], st + 32768u + bo);
            }
            #pragma unroll
            for (int nt = 0; nt < 4; nt++) {
                int p = nt >> 1, u = (nt & 1) << 1;
                mma4(d[nt], Ah, Bh[p][u], Bh[p][u + 1]);
                mma4(d[nt], Ah, Bl[p][u], Bl[p][u + 1]);
                mma4(d[nt], Al, Bh[p][u], Bh[p][u + 1]);
            }
        }

        issue(c + 2);
    }

    #pragma unroll
    for (int nt = 0; nt < 4; nt++) {
        int col  = n0 + cg * 32 + nt * 8 + (l & 3) * 2;
        int row0 = rg * 16 + (l >> 2);
        *(float2*)(outp + (size_t)row0 * ldo + col) = make_float2(d[nt][0], d[nt][1]);
        *(float2*)(outp + (size_t)(row0 + 8) * ldo + col) = make_float2(d[nt][2], d[nt][3]);
    }
}

// ---------------------------------------------------------------------------
// Phase A (block b, 512 threads) — R15 version (1 row/block)
// ---------------------------------------------------------------------------
static __device__ void phaseA(int b, int t,
                              const float* __restrict__ hcur,
                              const float* __restrict__ x,
                              const float* __restrict__ mem,
                              const float* __restrict__ Wk,
                              const float* __restrict__ bk,
                              const float* __restrict__ Wri,
                              const float* __restrict__ bri,
                              float* sm)
{
    float* hs    = sm;          // 1024
    float* ex    = sm + 1024;   // 1024
    float* kq    = sm + 2048;   // 64
    float* red   = sm + 2112;   // 512
    float* readv = sm + 2624;   // 64
    float* sred  = sm + 2688;   // 32

    const int tid  = threadIdx.x;
    const int warp = tid >> 5;
    const int lane = tid & 31;

    hs[tid]       = hcur[b * HH + tid];
    hs[tid + 512] = hcur[b * HH + tid + 512];
    __syncthreads();

    #pragma unroll
    for (int mi = 0; mi < 4; mi++) {
        int m = warp * 4 + mi;
        const float* wrow = Wk + (size_t)m * HH;
        float s = 0.f;
        #pragma unroll 8
        for (int k = lane; k < HH; k += 32) s += hs[k] * wrow[k];
        #pragma unroll
        for (int off = 16; off; off >>= 1) s += __shfl_down_sync(0xffffffffu, s, off);
        if (lane == 0) kq[m] = s + bk[m];
    }
    __syncthreads();

    float s0 = 0.f, s1 = 0.f;
    const float* mt = g_memT + tid;
    #pragma unroll 16
    for (int m = 0; m < MM; m++) {
        float kv = kq[m];
        const float* row = mt + m * PP;
        s0 += kv * row[0];
        s1 += kv * row[512];
    }
    float lmax = fmaxf(s0, s1);
    #pragma unroll
    for (int off = 16; off; off >>= 1)
        lmax = fmaxf(lmax, __shfl_xor_sync(0xffffffffu, lmax, off));
    if (lane == 0) sred[warp] = lmax;
    __syncthreads();
    float bmax = sred[0];
    #pragma unroll
    for (int w = 1; w < 16; w++) bmax = fmaxf(bmax, sred[w]);

    float e0 = expf(s0 - bmax), e1 = expf(s1 - bmax);
    ex[tid] = e0; ex[tid + 512] = e1;
    float lsum = e0 + e1;
    #pragma unroll
    for (int off = 16; off; off >>= 1)
        lsum += __shfl_xor_sync(0xffffffffu, lsum, off);
    if (lane == 0) sred[16 + warp] = lsum;
    __syncthreads();
    float bsum = 0.f;
    #pragma unroll
    for (int w = 0; w < 16; w++) bsum += sred[16 + w];

    {
        int m = tid & 63;
        int q = tid >> 6;
        const float* mp = mem + (size_t)(q * 128) * MM + m;
        const float* ep = ex + q * 128;
        float pr = 0.f;
        #pragma unroll 8
        for (int p = 0; p < 128; p++) pr += ep[p] * mp[(size_t)p * MM];
        red[q * 64 + m] = pr;
    }
    __syncthreads();
    if (tid < MM) {
        float s = 0.f;
        #pragma unroll
        for (int q = 0; q < 8; q++) s += red[q * 64 + tid];
        readv[tid] = s / bsum;
    }
    __syncthreads();

    {
        int i = tid;
        const float4* wr = (const float4*)(Wri + (size_t)i * MM);
        float s = bri[i];
        #pragma unroll
        for (int m4 = 0; m4 < 16; m4++) {
            float4 w = wr[m4];
            s += readv[m4 * 4 + 0] * w.x + readv[m4 * 4 + 1] * w.y
               + readv[m4 * 4 + 2] * w.z + readv[m4 * 4 + 3] * w.w;
        }
        float v = x[((size_t)b * TT + t) * II + i] + fmaxf(s, 0.f);
        float vn = __shfl_down_sync(0xffffffffu, v, 1);
        if ((i & 1) == 0) {
            uint32_t hi = pack2(v, vn);
            float r0 = v  - __uint_as_float(hi << 16);
            float r1 = vn - __uint_as_float(hi & 0xFFFF0000u);
            uint32_t lo = pack2(r0, r1);
            int kc = i >> 6, f2 = (i & 63) >> 1;
            int word = kc * 4096 + b * 32 + (f2 ^ ((b & 7) << 2));
            g_xpre[word]        = hi;
            g_xpre[word + 2048] = lo;
        }
    }
    __syncthreads();
}

// ---------------------------------------------------------------------------
// Persistent megakernel (schedule = R15)
// ---------------------------------------------------------------------------
__global__ void __launch_bounds__(NT, 1) ntm_persist(
    const float* __restrict__ x,    const float* __restrict__ mem,
    const float* __restrict__ Wk,   const float* __restrict__ bk,
    const float* __restrict__ Wri,  const float* __restrict__ bri,
    const float* __restrict__ Wih,  const float* __restrict__ Whh,
    const float* __restrict__ bih,  const float* __restrict__ bhh,
    const float* __restrict__ Wout, const float* __restrict__ bout,
    float* __restrict__ out)
{
    extern __shared__ __align__(16) char dsm[];     // 3 stages = 147,456 B
    __shared__ float sA[2720];
    const uint32_t sb = smem_u32(dsm);

    const int bid = blockIdx.x;
    const int tid = threadIdx.x;
    const int gid = bid * NT + tid;

    // ---- one-time init ----
    for (int e = gid; e < BB * HH; e += NB * NT) g_h[0][e] = 0.f;
    for (int e = gid; e < 16 * 4096; e += NB * NT) g_hpre[0][e] = 0u;
    for (int e = gid; e < PP * MM; e += NB * NT) {
        int p = e >> 6, m = e & 63;
        g_memT[m * PP + p] = mem[e];
    }
    for (int w = gid; w < 640 * 4096; w += NB * NT) {
        int blk = w >> 12, within = w & 4095;
        int r = within >> 5, sw = within & 31;
        int f2 = sw ^ ((r & 7) << 2);
        const float* src; int ldw, row, k;
        if (blk < 192) {
            int ct = blk >> 3, kc = blk & 7;
            src = Wih; ldw = II; row = ct * 128 + r; k = kc * 64 + f2 * 2;
        } else if (blk < 576) {
            int b2 = blk - 192, ct = b2 >> 4, kc = b2 & 15;
            src = Whh; ldw = HH; row = ct * 128 + r; k = kc * 64 + f2 * 2;
        } else {
            int b3 = blk - 576, ct = b3 >> 4, kc = b3 & 15;
            src = Wout; ldw = HH; row = ct * 128 + r; k = kc * 64 + f2 * 2;
        }
        float v0 = src[(size_t)row * ldw + k];
        float v1 = src[(size_t)row * ldw + k + 1];
        uint32_t hi = pack2(v0, v1);
        float r0 = v0 - __uint_as_float(hi << 16);
        float r1 = v1 - __uint_as_float(hi & 0xFFFF0000u);
        uint32_t lo = pack2(r0, r1);
        g_Wpre[(size_t)blk * 8192 + within]        = hi;
        g_Wpre[(size_t)blk * 8192 + 4096 + within] = lo;
    }
    gsync();

    for (int t = 0; t <= TT; t++) {
        const float* hcur = g_h[t & 1];
        const uint32_t* hpre = g_hpre[t & 1];

        // ---- S1: phaseA [0..63] || out(t-1) [64..79] || gh 0..67 [80..147]
        if (bid < 64) {
            if (t < TT) phaseA(bid, t, hcur, x, mem, Wk, bk, Wri, bri, sA);
        } else if (bid < 80) {
            if (t >= 1) {
                int j = bid - 64, ct = j >> 2, ks = j & 3;
                hjob(hpre + ks * 4 * 4096,
                     g_Wpre + (size_t)(576 + ct * 16 + ks * 4) * 8192,
                     4, g_cp[ks], OO, ct * 128, sb);
            }
        } else {
            if (t < TT) {
                int j = bid - 80, ct = j >> 2, ks = j & 3;
                hjob(hpre + ks * 4 * 4096,
                     g_Wpre + (size_t)(192 + ct * 16 + ks * 4) * 8192,
                     4, g_gh[ks], G3, ct * 128, sb);
            }
        }
        gsync();

        // ---- S2: gh 68..95 [0..27] || gi [28..75] || out combine [76..79]
        if (bid < 28) {
            if (t < TT) {
                int j = 68 + bid, ct = j >> 2, ks = j & 3;
                hjob(hpre + ks * 4 * 4096,
                     g_Wpre + (size_t)(192 + ct * 16 + ks * 4) * 8192,
                     4, g_gh[ks], G3, ct * 128, sb);
            }
        } else if (bid < 76) {
            if (t < TT) {
                int j = bid - 28, ct = j >> 1, ks = j & 1;
                hjob(g_xpre + ks * 4 * 4096,
                     g_Wpre + (size_t)(ct * 8 + ks * 4) * 8192,
                     4, g_gi[ks], G3, ct * 128, sb);
            }
        } else if (bid < 80) {
            if (t >= 1) {
                int idx = (bid - 76) * NT + tid;
                for (int e = idx; e < BB * OO; e += 4 * NT) {
                    int b = e >> 9, oc = e & (OO - 1);
                    float s = bout[oc] + g_cp[0][e] + g_cp[1][e]
                            + g_cp[2][e] + g_cp[3][e];
                    out[((size_t)b * TT + (t - 1)) * OO + oc] =
                        1.f / (1.f + expf(-s));
                }
            }
        }
        if (t == TT) break;
        gsync();

        // ---- S3: GRU -> h(t+1) f32 + bf16 image ----
        if (bid < 128) {
            float* hnew = g_h[(t + 1) & 1];
            uint32_t* hp = g_hpre[(t + 1) & 1];
            int e = gid;                          // 0..65535
            int b = e >> 10, c = e & 1023;
            size_t o = (size_t)b * G3 + c;
            float ir  = g_gi[0][o]        + g_gi[1][o]        + bih[c];
            float iz  = g_gi[0][o + 1024] + g_gi[1][o + 1024] + bih[1024 + c];
            float inn = g_gi[0][o + 2048] + g_gi[1][o + 2048] + bih[2048 + c];
            float hr = bhh[c], hz = bhh[1024 + c], hn = bhh[2048 + c];
            #pragma unroll
            for (int q = 0; q < 4; q++) {
                hr += g_gh[q][o];
                hz += g_gh[q][o + 1024];
                hn += g_gh[q][o + 2048];
            }
            float rg = 1.f / (1.f + expf(-(ir + hr)));
            float zg = 1.f / (1.f + expf(-(iz + hz)));
            float ng = tanhf(inn + rg * hn);
            float hv = (1.f - zg) * ng + zg * hcur[e];
            hnew[e] = hv;
            float vn = __shfl_down_sync(0xffffffffu, hv, 1);
            if ((e & 1) == 0) {
                uint32_t hi = pack2(hv, vn);
                float r0 = hv - __uint_as_float(hi << 16);
                float r1 = vn - __uint_as_float(hi & 0xFFFF0000u);
                uint32_t lo = pack2(r0, r1);
                int kc = c >> 6, f2 = (c & 63) >> 1;
                int word = kc * 4096 + b * 32 + (f2 ^ ((b & 7) << 2));
                hp[word]        = hi;
                hp[word + 2048] = lo;
            }
        }
        gsync();
    }
}

extern "C" void kernel_launch(void* const* d_in, const int* in_sizes, int n_in,
                              void* d_out, int out_size)
{
    const float* x    = (const float*)d_in[0];
    const float* mem  = (const float*)d_in[1];
    const float* Wk   = (const float*)d_in[2];
    const float* bk   = (const float*)d_in[3];
    const float* Wri  = (const float*)d_in[4];
    const float* bri  = (const float*)d_in[5];
    const float* Wih  = (const float*)d_in[6];
    const float* Whh  = (const float*)d_in[7];
    const float* bih  = (const float*)d_in[8];
    const float* bhh  = (const float*)d_in[9];
    const float* Wout = (const float*)d_in[10];
    const float* bout = (const float*)d_in[11];

    static int once = 0;
    const int smem_bytes = 3 * STAGE_BYTES;   // 147,456
    if (!once) {
        cudaFuncSetAttribute(ntm_persist,
                             cudaFuncAttributeMaxDynamicSharedMemorySize,
                             smem_bytes);
        once = 1;
    }

    ntm_persist<<<NB, NT, smem_bytes>>>(x, mem, Wk, bk, Wri, bri, Wih, Whh,
                                        bih, bhh, Wout, bout, (float*)d_out);
}